// round 12
// baseline (speedup 1.0000x reference)
#include <cuda_runtime.h>
#include <stdint.h>

#define NCOLS   24576
#define THREADS 512
#define NWARPS  (THREADS / 32)            // 16
#define EPT     (NCOLS / (THREADS * 4))   // 12 uint4 per thread
#define HWORDS  2048                      // hist / candidate region (words)
#define CAP     1000                      // candidate capacity (u64 -> 2000 words <= HWORDS)
// smem words: hist + warp-totals + select-out(4) + vars(8)   (~8.3 KB total)
#define SMEM_WORDS (HWORDS + NWARPS + 4 + 8)
#define SMEM_BYTES (SMEM_WORDS * 4)

// Static candidate floor: 2.5f (key 0xC0200000).
// For N(0,1) rows of 24576: E[count >= 2.5] ~ 153 (sigma ~12) -> P(n < 64) ~ 3e-13/row.
// Any other distribution (n<k or n>CAP) is caught by the exact radix fallback.
#define FGUESS  2.5f
#define KGUESS  0xC0200000u

// ---- order-preserving float<->key transform (bigger key = bigger float), branch-free
__device__ __forceinline__ uint32_t f2key(float f) {
    uint32_t b = __float_as_uint(f);
    uint32_t m = (uint32_t)(((int32_t)b) >> 31) | 0x80000000u;  // neg: ~0, pos: 0x80000000
    return b ^ m;
}
__device__ __forceinline__ float key2f(uint32_t k) {
    uint32_t m = (~(uint32_t)(((int32_t)k) >> 31)) | 0x80000000u;
    return __uint_as_float(k ^ m);
}

// Block-wide suffix select over histogram h (FALLBACK only): thread t owns bins
// [t*G, t*G+G). Finds bin b = max{b : count(bins >= b) >= rank}; writes
// s_sel[0]=bin, s_sel[1]=rank-within-bin (1-based), s_sel[2]=bin count.
__device__ __forceinline__ void suffix_select(
    const uint32_t* h, int G, int nbins, int rank,
    uint32_t* s_wtot, uint32_t* s_sel)
{
    const int t = threadIdx.x, lane = t & 31, warp = t >> 5;
    int v = 0;
    if (t * G < nbins) {
        #pragma unroll
        for (int j = 0; j < 4; j++)
            if (j < G) v += (int)h[t * G + j];
    }
    int s = v;
    #pragma unroll
    for (int d = 1; d < 32; d <<= 1) {
        int o = __shfl_down_sync(0xffffffffu, s, d);
        if (lane + d < 32) s += o;
    }
    if (lane == 0) s_wtot[warp] = (uint32_t)s;
    __syncthreads();
    if (warp == 0) {
        int wv = (lane < NWARPS) ? (int)s_wtot[lane] : 0;
        int ws = wv;
        #pragma unroll
        for (int d = 1; d < 32; d <<= 1) {
            int o = __shfl_down_sync(0xffffffffu, ws, d);
            if (lane + d < 32) ws += o;
        }
        if (lane < NWARPS) s_wtot[lane] = (uint32_t)(ws - wv);
    }
    __syncthreads();
    int S = s + (int)s_wtot[warp];
    int above = S - v;
    if (t * G < nbins && S >= rank && above < rank) {
        int cum = above;
        for (int j = G - 1; j >= 0; j--) {
            int c = (int)h[t * G + j];
            if (cum + c >= rank) {
                s_sel[0] = (uint32_t)(t * G + j);
                s_sel[1] = (uint32_t)(rank - cum);
                s_sel[2] = (uint32_t)c;
                break;
            }
            cum += c;
        }
    }
    __syncthreads();
}

__device__ __forceinline__ void clear_hist(uint32_t* h) {
    #pragma unroll
    for (int i = 0; i < HWORDS / THREADS; i++) h[i * THREADS + threadIdx.x] = 0;
}

__device__ __forceinline__ uint4 load_keys(const float4* xin, int pos) {
    float4 v = __ldg(&xin[pos]);
    uint4 kk;
    kk.x = f2key(v.x); kk.y = f2key(v.y); kk.z = f2key(v.z); kk.w = f2key(v.w);
    return kk;
}

__global__ void __launch_bounds__(THREADS, 4)
topk_filter_kernel(const float* __restrict__ x, const int* __restrict__ kptr,
                   float* __restrict__ out)
{
    extern __shared__ uint32_t sm[];
    uint32_t* h      = sm;                      // HWORDS (fallback hist / candidate composites)
    uint32_t* s_wtot = h + HWORDS;              // NWARPS
    uint32_t* s_sel  = s_wtot + NWARPS;         // 4
    uint32_t* s_var  = s_sel + 4;               // 8: [0]=cand ctr, [1]=cut lo, [2]=cut hi, [3]=bsearch ctr
    unsigned long long* cand = (unsigned long long*)h;   // CAP u64 composites

    const int t    = threadIdx.x;
    const int lane = t & 31;
    const int k    = *kptr;

    const float4* xin   = (const float4*)(x   + (size_t)blockIdx.x * NCOLS);
    float4*       xout  = (float4*)      (out + (size_t)blockIdx.x * NCOLS);
    float*        outf  = out + (size_t)blockIdx.x * NCOLS;

    if (k >= NCOLS) {
        #pragma unroll 4
        for (int i = 0; i < EPT; i++) xout[i * THREADS + t] = __ldcs(&xin[i * THREADS + t]);
        return;
    }
    if (k <= 0) {
        float4 z = make_float4(0.f, 0.f, 0.f, 0.f);
        #pragma unroll 4
        for (int i = 0; i < EPT; i++) __stcs(&xout[i * THREADS + t], z);
        return;
    }

    if (t == 0) s_var[0] = 0;
    __syncthreads();   // counter visible before any append

    // ---------------- P0: single streaming pass: read + flag mask + ZERO the output ----
    // Loads allocate in L2 (flagged-quad revisits hit L2). Zero-stores are independent
    // of the loads, so both streams pipeline. The few kept values are scattered in P3.
    const float4 zero4 = make_float4(0.f, 0.f, 0.f, 0.f);
    uint32_t qmask = 0;   // bit i set iff quad i may contain a candidate
    #pragma unroll 4
    for (int i = 0; i < EPT; i++) {
        float4 v = __ldg(&xin[i * THREADS + t]);
        __stcs(&xout[i * THREADS + t], zero4);
        float qmax = fmaxf(fmaxf(v.x, v.y), fmaxf(v.z, v.w));
        qmask |= (qmax >= FGUESS ? 1u : 0u) << i;
    }

    // ---------------- P1: revisit flagged quads (~0.15/thread) from L2; exact keys here
    while (qmask) {
        int i = __ffs(qmask) - 1;
        qmask &= qmask - 1u;
        uint4 kk = load_keys(xin, i * THREADS + t);
        uint32_t base = (uint32_t)(i * THREADS + t) * 4u;
        if (kk.x >= KGUESS) { unsigned p = atomicAdd(&s_var[0], 1u); if (p < CAP) cand[p] = ((unsigned long long)kk.x << 16) | (unsigned long long)(0xFFFFu - base); }
        if (kk.y >= KGUESS) { unsigned p = atomicAdd(&s_var[0], 1u); if (p < CAP) cand[p] = ((unsigned long long)kk.y << 16) | (unsigned long long)(0xFFFFu - (base + 1u)); }
        if (kk.z >= KGUESS) { unsigned p = atomicAdd(&s_var[0], 1u); if (p < CAP) cand[p] = ((unsigned long long)kk.z << 16) | (unsigned long long)(0xFFFFu - (base + 2u)); }
        if (kk.w >= KGUESS) { unsigned p = atomicAdd(&s_var[0], 1u); if (p < CAP) cand[p] = ((unsigned long long)kk.w << 16) | (unsigned long long)(0xFFFFu - (base + 3u)); }
    }
    __syncthreads();   // candidates complete; also orders P0 zero-stores before P3 scatter
    const unsigned n = s_var[0];

    if (n >= (unsigned)k && n <= CAP) {
        // ------------- exact k-th by composite (key desc, idx asc): tight rank count ----
        for (unsigned i = t; i < n; i += THREADS) {
            unsigned long long cki = cand[i];
            int cnt = 0;
            for (unsigned j = 0; j < n; j++) cnt += (cand[j] > cki);
            if (cnt == k - 1) {   // exactly one winner (composites distinct)
                s_var[1] = (uint32_t)(cki & 0xFFFFFFFFu);
                s_var[2] = (uint32_t)(cki >> 32);
            }
        }
        __syncthreads();
        const unsigned long long cut =
            ((unsigned long long)s_var[2] << 32) | (unsigned long long)s_var[1];

        // ------------- P3: scatter the exactly-k kept values over the zeros -------------
        // Kept set == { cand[i] : cand[i] >= cut }  (k-1 strictly greater + the cut itself)
        for (unsigned i = t; i < n; i += THREADS) {
            unsigned long long c = cand[i];
            if (c >= cut) {
                uint32_t idx = 0xFFFFu - (uint32_t)(c & 0xFFFFu);
                outf[idx] = key2f((uint32_t)(c >> 16));
            }
        }
        return;
    }

    // ---------------- FALLBACK: exact 3-pass radix select (re-reads from L2) --------
    __syncthreads();
    clear_hist(h);
    __syncthreads();
    #pragma unroll 4
    for (int i = 0; i < EPT; i++) {
        uint4 kk = load_keys(xin, i * THREADS + t);
        atomicAdd(&h[kk.x >> 21], 1u);
        atomicAdd(&h[kk.y >> 21], 1u);
        atomicAdd(&h[kk.z >> 21], 1u);
        atomicAdd(&h[kk.w >> 21], 1u);
    }
    __syncthreads();
    suffix_select(h, 4, 2048, k, s_wtot, s_sel);
    const uint32_t b1 = s_sel[0];
    const int      k1 = (int)s_sel[1];

    clear_hist(h);
    __syncthreads();
    #pragma unroll 4
    for (int i = 0; i < EPT; i++) {
        uint4 kk = load_keys(xin, i * THREADS + t);
        if ((kk.x >> 21) == b1) atomicAdd(&h[(kk.x >> 10) & 0x7FFu], 1u);
        if ((kk.y >> 21) == b1) atomicAdd(&h[(kk.y >> 10) & 0x7FFu], 1u);
        if ((kk.z >> 21) == b1) atomicAdd(&h[(kk.z >> 10) & 0x7FFu], 1u);
        if ((kk.w >> 21) == b1) atomicAdd(&h[(kk.w >> 10) & 0x7FFu], 1u);
    }
    __syncthreads();
    suffix_select(h, 4, 2048, k1, s_wtot, s_sel);
    const uint32_t prefix22 = (b1 << 11) | s_sel[0];
    const int      k2       = (int)s_sel[1];

    clear_hist(h);
    __syncthreads();
    #pragma unroll 4
    for (int i = 0; i < EPT; i++) {
        uint4 kk = load_keys(xin, i * THREADS + t);
        if ((kk.x >> 10) == prefix22) atomicAdd(&h[kk.x & 0x3FFu], 1u);
        if ((kk.y >> 10) == prefix22) atomicAdd(&h[kk.y & 0x3FFu], 1u);
        if ((kk.z >> 10) == prefix22) atomicAdd(&h[kk.z & 0x3FFu], 1u);
        if ((kk.w >> 10) == prefix22) atomicAdd(&h[kk.w & 0x3FFu], 1u);
    }
    __syncthreads();
    suffix_select(h, 2, 1024, k2, s_wtot, s_sel);
    const uint32_t Tkey = (prefix22 << 10) | s_sel[0];
    const int m    = (int)s_sel[1];
    const int n_eq = (int)s_sel[2];

    uint32_t idx_cut = 0xFFFFFFFFu;
    if (n_eq != m) {
        // counting binary search on index for the tie cut
        int lo = 0, hi = NCOLS - 1;
        while (lo < hi) {
            int mid = (lo + hi) >> 1;
            if (t == 0) s_var[3] = 0;
            __syncthreads();
            int local = 0;
            #pragma unroll 4
            for (int i = 0; i < EPT; i++) {
                uint4 kk = load_keys(xin, i * THREADS + t);
                int base = (i * THREADS + t) * 4;
                local += (kk.x == Tkey && base     <= mid);
                local += (kk.y == Tkey && base + 1 <= mid);
                local += (kk.z == Tkey && base + 2 <= mid);
                local += (kk.w == Tkey && base + 3 <= mid);
            }
            #pragma unroll
            for (int d = 16; d; d >>= 1) local += __shfl_down_sync(0xffffffffu, local, d);
            if (lane == 0 && local) atomicAdd(&s_var[3], (uint32_t)local);
            __syncthreads();
            if ((int)s_var[3] >= m) hi = mid; else lo = mid + 1;
            __syncthreads();
        }
        idx_cut = (uint32_t)lo;
    }

    // fallback output: zeros are already in place; store only the kept entries
    #pragma unroll 4
    for (int i = 0; i < EPT; i++) {
        float4 v = __ldg(&xin[i * THREADS + t]);
        uint4 kk;
        kk.x = f2key(v.x); kk.y = f2key(v.y); kk.z = f2key(v.z); kk.w = f2key(v.w);
        uint32_t base = (uint32_t)(i * THREADS + t) * 4u;
        if (kk.x > Tkey || (kk.x == Tkey && base      <= idx_cut)) outf[base]      = v.x;
        if (kk.y > Tkey || (kk.y == Tkey && base + 1u <= idx_cut)) outf[base + 1u] = v.y;
        if (kk.z > Tkey || (kk.z == Tkey && base + 2u <= idx_cut)) outf[base + 2u] = v.z;
        if (kk.w > Tkey || (kk.w == Tkey && base + 3u <= idx_cut)) outf[base + 3u] = v.w;
    }
}

extern "C" void kernel_launch(void* const* d_in, const int* in_sizes, int n_in,
                              void* d_out, int out_size)
{
    int xi = 0, ki = 1;
    if (n_in >= 2 && in_sizes[1] > in_sizes[0]) { xi = 1; ki = 0; }

    const float* x  = (const float*)d_in[xi];
    const int*   kp = (const int*)  d_in[ki];
    float*       out = (float*)d_out;

    int nrows = in_sizes[xi] / NCOLS;

    cudaFuncSetAttribute(topk_filter_kernel,
                         cudaFuncAttributeMaxDynamicSharedMemorySize, SMEM_BYTES);
    topk_filter_kernel<<<nrows, THREADS, SMEM_BYTES>>>(x, kp, out);
}

// round 13
// speedup vs baseline: 1.0398x; 1.0398x over previous
#include <cuda_runtime.h>
#include <stdint.h>

#define NCOLS   24576
#define THREADS 512
#define NWARPS  (THREADS / 32)            // 16
#define EPT     (NCOLS / (THREADS * 4))   // 12 uint4 per thread
#define HWORDS  2048                      // hist / candidate region (words)
#define CAP     1000                      // candidate capacity (u64 -> 2000 words <= HWORDS)
// smem words: hist + warp-totals + select-out(4) + vars(8)   (~8.3 KB total)
#define SMEM_WORDS (HWORDS + NWARPS + 4 + 8)
#define SMEM_BYTES (SMEM_WORDS * 4)

// Static candidate floor: 2.5f (key 0xC0200000).
// For N(0,1) rows of 24576: E[count >= 2.5] ~ 153 (sigma ~12) -> P(n < 64) ~ 3e-13/row.
// Any other distribution (n<k or n>CAP) is caught by the exact radix fallback.
#define FGUESS  2.5f
#define KGUESS  0xC0200000u

// ---- order-preserving float<->key transform (bigger key = bigger float), branch-free
__device__ __forceinline__ uint32_t f2key(float f) {
    uint32_t b = __float_as_uint(f);
    uint32_t m = (uint32_t)(((int32_t)b) >> 31) | 0x80000000u;  // neg: ~0, pos: 0x80000000
    return b ^ m;
}
__device__ __forceinline__ float key2f(uint32_t k) {
    uint32_t m = (~(uint32_t)(((int32_t)k) >> 31)) | 0x80000000u;
    return __uint_as_float(k ^ m);
}

// Block-wide suffix select over histogram h (FALLBACK only): thread t owns bins
// [t*G, t*G+G). Finds bin b = max{b : count(bins >= b) >= rank}; writes
// s_sel[0]=bin, s_sel[1]=rank-within-bin (1-based), s_sel[2]=bin count.
__device__ __forceinline__ void suffix_select(
    const uint32_t* h, int G, int nbins, int rank,
    uint32_t* s_wtot, uint32_t* s_sel)
{
    const int t = threadIdx.x, lane = t & 31, warp = t >> 5;
    int v = 0;
    if (t * G < nbins) {
        #pragma unroll
        for (int j = 0; j < 4; j++)
            if (j < G) v += (int)h[t * G + j];
    }
    int s = v;
    #pragma unroll
    for (int d = 1; d < 32; d <<= 1) {
        int o = __shfl_down_sync(0xffffffffu, s, d);
        if (lane + d < 32) s += o;
    }
    if (lane == 0) s_wtot[warp] = (uint32_t)s;
    __syncthreads();
    if (warp == 0) {
        int wv = (lane < NWARPS) ? (int)s_wtot[lane] : 0;
        int ws = wv;
        #pragma unroll
        for (int d = 1; d < 32; d <<= 1) {
            int o = __shfl_down_sync(0xffffffffu, ws, d);
            if (lane + d < 32) ws += o;
        }
        if (lane < NWARPS) s_wtot[lane] = (uint32_t)(ws - wv);
    }
    __syncthreads();
    int S = s + (int)s_wtot[warp];
    int above = S - v;
    if (t * G < nbins && S >= rank && above < rank) {
        int cum = above;
        for (int j = G - 1; j >= 0; j--) {
            int c = (int)h[t * G + j];
            if (cum + c >= rank) {
                s_sel[0] = (uint32_t)(t * G + j);
                s_sel[1] = (uint32_t)(rank - cum);
                s_sel[2] = (uint32_t)c;
                break;
            }
            cum += c;
        }
    }
    __syncthreads();
}

__device__ __forceinline__ void clear_hist(uint32_t* h) {
    #pragma unroll
    for (int i = 0; i < HWORDS / THREADS; i++) h[i * THREADS + threadIdx.x] = 0;
}

__device__ __forceinline__ uint4 load_keys(const float4* xin, int pos) {
    float4 v = __ldg(&xin[pos]);
    uint4 kk;
    kk.x = f2key(v.x); kk.y = f2key(v.y); kk.z = f2key(v.z); kk.w = f2key(v.w);
    return kk;
}

__global__ void __launch_bounds__(THREADS, 3)
topk_filter_kernel(const float* __restrict__ x, const int* __restrict__ kptr,
                   float* __restrict__ out)
{
    extern __shared__ uint32_t sm[];
    uint32_t* h      = sm;                      // HWORDS (fallback hist / candidate composites)
    uint32_t* s_wtot = h + HWORDS;              // NWARPS
    uint32_t* s_sel  = s_wtot + NWARPS;         // 4
    uint32_t* s_var  = s_sel + 4;               // 8: [0]=cand ctr, [1]=cut lo, [2]=cut hi, [3]=bsearch ctr
    unsigned long long* cand = (unsigned long long*)h;   // CAP u64 composites

    const int t    = threadIdx.x;
    const int lane = t & 31;
    const int k    = *kptr;

    const float4* xin   = (const float4*)(x   + (size_t)blockIdx.x * NCOLS);
    float4*       xout  = (float4*)      (out + (size_t)blockIdx.x * NCOLS);
    float*        outf  = out + (size_t)blockIdx.x * NCOLS;

    if (k >= NCOLS) {
        #pragma unroll 4
        for (int i = 0; i < EPT; i++) xout[i * THREADS + t] = __ldcs(&xin[i * THREADS + t]);
        return;
    }
    if (k <= 0) {
        float4 z = make_float4(0.f, 0.f, 0.f, 0.f);
        #pragma unroll 4
        for (int i = 0; i < EPT; i++) __stcs(&xout[i * THREADS + t], z);
        return;
    }

    if (t == 0) s_var[0] = 0;
    __syncthreads();   // counter visible before any append

    // ---------------- P0: single streaming pass: read + flag mask + ZERO the output ----
    // Two loads issued back-to-back per iteration (front-batched MLP), then the two
    // independent zero-stores, then flag math. Loads allocate in L2 so the flagged-quad
    // revisits in P1 hit L2. The few kept values are scattered in P3.
    const float4 zero4 = make_float4(0.f, 0.f, 0.f, 0.f);
    uint32_t qmask = 0;   // bit i set iff quad i may contain a candidate
    #pragma unroll 2
    for (int i = 0; i < EPT; i += 2) {
        float4 v0 = __ldg(&xin[i * THREADS + t]);
        float4 v1 = __ldg(&xin[(i + 1) * THREADS + t]);
        __stcs(&xout[i * THREADS + t],       zero4);
        __stcs(&xout[(i + 1) * THREADS + t], zero4);
        float m0 = fmaxf(fmaxf(v0.x, v0.y), fmaxf(v0.z, v0.w));
        float m1 = fmaxf(fmaxf(v1.x, v1.y), fmaxf(v1.z, v1.w));
        qmask |= (m0 >= FGUESS ? 1u : 0u) << i;
        qmask |= (m1 >= FGUESS ? 2u : 0u) << i;
    }

    // ---------------- P1: revisit flagged quads (~0.15/thread) from L2; exact keys here
    while (qmask) {
        int i = __ffs(qmask) - 1;
        qmask &= qmask - 1u;
        uint4 kk = load_keys(xin, i * THREADS + t);
        uint32_t base = (uint32_t)(i * THREADS + t) * 4u;
        if (kk.x >= KGUESS) { unsigned p = atomicAdd(&s_var[0], 1u); if (p < CAP) cand[p] = ((unsigned long long)kk.x << 16) | (unsigned long long)(0xFFFFu - base); }
        if (kk.y >= KGUESS) { unsigned p = atomicAdd(&s_var[0], 1u); if (p < CAP) cand[p] = ((unsigned long long)kk.y << 16) | (unsigned long long)(0xFFFFu - (base + 1u)); }
        if (kk.z >= KGUESS) { unsigned p = atomicAdd(&s_var[0], 1u); if (p < CAP) cand[p] = ((unsigned long long)kk.z << 16) | (unsigned long long)(0xFFFFu - (base + 2u)); }
        if (kk.w >= KGUESS) { unsigned p = atomicAdd(&s_var[0], 1u); if (p < CAP) cand[p] = ((unsigned long long)kk.w << 16) | (unsigned long long)(0xFFFFu - (base + 3u)); }
    }
    __syncthreads();   // candidates complete; also orders P0 zero-stores before P3 scatter
    const unsigned n = s_var[0];

    if (n >= (unsigned)k && n <= CAP) {
        // ------------- exact k-th by composite (key desc, idx asc): tight rank count ----
        for (unsigned i = t; i < n; i += THREADS) {
            unsigned long long cki = cand[i];
            int cnt = 0;
            for (unsigned j = 0; j < n; j++) cnt += (cand[j] > cki);
            if (cnt == k - 1) {   // exactly one winner (composites distinct)
                s_var[1] = (uint32_t)(cki & 0xFFFFFFFFu);
                s_var[2] = (uint32_t)(cki >> 32);
            }
        }
        __syncthreads();
        const unsigned long long cut =
            ((unsigned long long)s_var[2] << 32) | (unsigned long long)s_var[1];

        // ------------- P3: scatter the exactly-k kept values over the zeros -------------
        // Kept set == { cand[i] : cand[i] >= cut }  (k-1 strictly greater + the cut itself)
        for (unsigned i = t; i < n; i += THREADS) {
            unsigned long long c = cand[i];
            if (c >= cut) {
                uint32_t idx = 0xFFFFu - (uint32_t)(c & 0xFFFFu);
                outf[idx] = key2f((uint32_t)(c >> 16));
            }
        }
        return;
    }

    // ---------------- FALLBACK: exact 3-pass radix select (re-reads from L2) --------
    __syncthreads();
    clear_hist(h);
    __syncthreads();
    #pragma unroll 4
    for (int i = 0; i < EPT; i++) {
        uint4 kk = load_keys(xin, i * THREADS + t);
        atomicAdd(&h[kk.x >> 21], 1u);
        atomicAdd(&h[kk.y >> 21], 1u);
        atomicAdd(&h[kk.z >> 21], 1u);
        atomicAdd(&h[kk.w >> 21], 1u);
    }
    __syncthreads();
    suffix_select(h, 4, 2048, k, s_wtot, s_sel);
    const uint32_t b1 = s_sel[0];
    const int      k1 = (int)s_sel[1];

    clear_hist(h);
    __syncthreads();
    #pragma unroll 4
    for (int i = 0; i < EPT; i++) {
        uint4 kk = load_keys(xin, i * THREADS + t);
        if ((kk.x >> 21) == b1) atomicAdd(&h[(kk.x >> 10) & 0x7FFu], 1u);
        if ((kk.y >> 21) == b1) atomicAdd(&h[(kk.y >> 10) & 0x7FFu], 1u);
        if ((kk.z >> 21) == b1) atomicAdd(&h[(kk.z >> 10) & 0x7FFu], 1u);
        if ((kk.w >> 21) == b1) atomicAdd(&h[(kk.w >> 10) & 0x7FFu], 1u);
    }
    __syncthreads();
    suffix_select(h, 4, 2048, k1, s_wtot, s_sel);
    const uint32_t prefix22 = (b1 << 11) | s_sel[0];
    const int      k2       = (int)s_sel[1];

    clear_hist(h);
    __syncthreads();
    #pragma unroll 4
    for (int i = 0; i < EPT; i++) {
        uint4 kk = load_keys(xin, i * THREADS + t);
        if ((kk.x >> 10) == prefix22) atomicAdd(&h[kk.x & 0x3FFu], 1u);
        if ((kk.y >> 10) == prefix22) atomicAdd(&h[kk.y & 0x3FFu], 1u);
        if ((kk.z >> 10) == prefix22) atomicAdd(&h[kk.z & 0x3FFu], 1u);
        if ((kk.w >> 10) == prefix22) atomicAdd(&h[kk.w & 0x3FFu], 1u);
    }
    __syncthreads();
    suffix_select(h, 2, 1024, k2, s_wtot, s_sel);
    const uint32_t Tkey = (prefix22 << 10) | s_sel[0];
    const int m    = (int)s_sel[1];
    const int n_eq = (int)s_sel[2];

    uint32_t idx_cut = 0xFFFFFFFFu;
    if (n_eq != m) {
        // counting binary search on index for the tie cut
        int lo = 0, hi = NCOLS - 1;
        while (lo < hi) {
            int mid = (lo + hi) >> 1;
            if (t == 0) s_var[3] = 0;
            __syncthreads();
            int local = 0;
            #pragma unroll 4
            for (int i = 0; i < EPT; i++) {
                uint4 kk = load_keys(xin, i * THREADS + t);
                int base = (i * THREADS + t) * 4;
                local += (kk.x == Tkey && base     <= mid);
                local += (kk.y == Tkey && base + 1 <= mid);
                local += (kk.z == Tkey && base + 2 <= mid);
                local += (kk.w == Tkey && base + 3 <= mid);
            }
            #pragma unroll
            for (int d = 16; d; d >>= 1) local += __shfl_down_sync(0xffffffffu, local, d);
            if (lane == 0 && local) atomicAdd(&s_var[3], (uint32_t)local);
            __syncthreads();
            if ((int)s_var[3] >= m) hi = mid; else lo = mid + 1;
            __syncthreads();
        }
        idx_cut = (uint32_t)lo;
    }

    // fallback output: zeros are already in place; store only the kept entries
    #pragma unroll 4
    for (int i = 0; i < EPT; i++) {
        float4 v = __ldg(&xin[i * THREADS + t]);
        uint4 kk;
        kk.x = f2key(v.x); kk.y = f2key(v.y); kk.z = f2key(v.z); kk.w = f2key(v.w);
        uint32_t base = (uint32_t)(i * THREADS + t) * 4u;
        if (kk.x > Tkey || (kk.x == Tkey && base      <= idx_cut)) outf[base]      = v.x;
        if (kk.y > Tkey || (kk.y == Tkey && base + 1u <= idx_cut)) outf[base + 1u] = v.y;
        if (kk.z > Tkey || (kk.z == Tkey && base + 2u <= idx_cut)) outf[base + 2u] = v.z;
        if (kk.w > Tkey || (kk.w == Tkey && base + 3u <= idx_cut)) outf[base + 3u] = v.w;
    }
}

extern "C" void kernel_launch(void* const* d_in, const int* in_sizes, int n_in,
                              void* d_out, int out_size)
{
    int xi = 0, ki = 1;
    if (n_in >= 2 && in_sizes[1] > in_sizes[0]) { xi = 1; ki = 0; }

    const float* x  = (const float*)d_in[xi];
    const int*   kp = (const int*)  d_in[ki];
    float*       out = (float*)d_out;

    int nrows = in_sizes[xi] / NCOLS;

    cudaFuncSetAttribute(topk_filter_kernel,
                         cudaFuncAttributeMaxDynamicSharedMemorySize, SMEM_BYTES);
    topk_filter_kernel<<<nrows, THREADS, SMEM_BYTES>>>(x, kp, out);
}